// round 12
// baseline (speedup 1.0000x reference)
#include <cuda_runtime.h>
#include <math.h>
#include <stdint.h>

// ---------------- problem constants ----------------
#define W     8192      // words
#define LC    16        // chars per word (padded)
#define CD    100       // char emb dim
#define CDP   128       // padded to %32 for tensor GEMM
#define WD    300       // word emb dim
#define HD    512       // hidden dim (bi)
#define HH    256       // per-direction hidden
#define G4    1024      // 4*HH gates
#define WDIN  812       // WD + HD
#define WDINP 832       // padded to %32
#define T1    48
#define T2    32

#define CLUST    8      // word-lstm CTAs per direction (one cluster)
#define CELLS    32     // cells per CTA

#define ALN __align__(16)

// smem layout constants for GEMM (floats)
#define KCH   32
#define RPAD  36
#define ABUF  (128 * RPAD)
#define BUFSZ (2 * ABUF)
#define GEMM_SMEM_BYTES (2 * BUFSZ * 4)   // 73728 B

// ---------------- static device scratch (no cudaMalloc allowed) ----------------
__device__ ALN float g_Xc[(size_t)LC * W * CDP];
__device__ ALN float g_XGf[(size_t)LC * W * G4];      // char input gates, fwd
__device__ ALN float g_XGb[(size_t)LC * W * G4];      // char input gates, bwd
__device__ ALN float g_Gc[2][(size_t)W * G4];         // per-step gate scratch (both dirs)
__device__ ALN float g_HC[4][(size_t)W * HH];         // Hf, Hb, Cf, Cb
__device__ ALN float g_WX[(size_t)W * WDINP];
__device__ ALN float g_XGw[(size_t)2 * W * G4];
__device__ ALN float g_OUT[(size_t)W * HD];
__device__ ALN float g_WihC[2][G4 * CDP];
__device__ ALN float g_WihW[2][G4 * WDINP];
__device__ ALN float g_bias[4][G4];

__device__ __forceinline__ float fast_sigmoid(float x) {
    return __fdividef(1.0f, 1.0f + __expf(-x));
}
__device__ __forceinline__ float fast_tanh(float x) {
    return 1.0f - __fdividef(2.0f, __expf(2.0f * x) + 1.0f);
}

__device__ __forceinline__ uint32_t smem_u32(const void* p) {
    uint32_t a;
    asm("{ .reg .u64 t; cvta.to.shared.u64 t, %1; cvt.u32.u64 %0, t; }" : "=r"(a) : "l"(p));
    return a;
}
__device__ __forceinline__ uint32_t to_tf32(float x) {
    uint32_t u;
    asm("cvt.rna.tf32.f32 %0, %1;" : "=r"(u) : "f"(x));
    return u;
}
#define CP_ASYNC16(dst, src) \
    asm volatile("cp.async.cg.shared.global [%0], [%1], 16;" :: "r"(dst), "l"(src) : "memory")
#define CP_COMMIT()  asm volatile("cp.async.commit_group;" ::: "memory")
#define CP_WAIT(n)   asm volatile("cp.async.wait_group %0;" :: "n"(n) : "memory")

// cluster barrier (split) and DSMEM store
#define CLUSTER_ARRIVE() asm volatile("barrier.cluster.arrive.aligned;" ::: "memory")
#define CLUSTER_WAIT()   asm volatile("barrier.cluster.wait.aligned;" ::: "memory")
#define ST_CLUSTER_F32(local_addr, rank, val)                                         \
    asm volatile("{\n\t.reg .b32 ra;\n\t"                                             \
                 "mapa.shared::cluster.u32 ra, %0, %1;\n\t"                           \
                 "st.shared::cluster.f32 [ra], %2;\n\t}"                              \
                 :: "r"(local_addr), "r"(rank), "f"(val) : "memory")

// ---------------- TF32 mma.sync dual GEMM ----------------
__global__ __launch_bounds__(256, 2)
void gemm_mma_dual_kernel(const float* __restrict__ A0, const float* __restrict__ A1,
                          const float* __restrict__ B0, const float* __restrict__ B1,
                          const float* __restrict__ bias0, const float* __restrict__ bias1,
                          const float* __restrict__ D0, const float* __restrict__ D1,
                          float* __restrict__ C0, float* __restrict__ C1,
                          int N, int K)
{
    extern __shared__ ALN float smem[];

    const int tid = threadIdx.x;
    const int lane = tid & 31, wid = tid >> 5;
    const int wm = wid & 1, wn = wid >> 1;
    const int bx = blockIdx.x, by = blockIdx.y, bz = blockIdx.z;

    const float* A    = bz ? A1 : A0;
    const float* B    = bz ? B1 : B0;
    const float* bias = bz ? bias1 : bias0;
    const float* Dadd = bz ? D1 : D0;
    float*       C    = bz ? C1 : C0;

    const float* Abase = A + (size_t)(by * 128) * K;
    const float* Bbase = B + (size_t)(bx * 128) * K;

    float acc[4][4][4];
#pragma unroll
    for (int i = 0; i < 4; i++)
#pragma unroll
        for (int j = 0; j < 4; j++)
#pragma unroll
            for (int q = 0; q < 4; q++) acc[i][j][q] = 0.0f;

    const int nkt = K >> 5;

    {
        float* dst = smem;
#pragma unroll
        for (int i = 0; i < 4; i++) {
            int f = tid + i * 256;
            int row = f >> 3, c4 = f & 7;
            CP_ASYNC16(smem_u32(dst + row * RPAD + c4 * 4), Abase + (size_t)row * K + c4 * 4);
            CP_ASYNC16(smem_u32(dst + ABUF + row * RPAD + c4 * 4), Bbase + (size_t)row * K + c4 * 4);
        }
        CP_COMMIT();
    }

    for (int kt = 0; kt < nkt; kt++) {
        if (kt + 1 < nkt) {
            float* dst = smem + ((kt + 1) & 1) * BUFSZ;
            const float* Ak = Abase + (kt + 1) * KCH;
            const float* Bk = Bbase + (kt + 1) * KCH;
#pragma unroll
            for (int i = 0; i < 4; i++) {
                int f = tid + i * 256;
                int row = f >> 3, c4 = f & 7;
                CP_ASYNC16(smem_u32(dst + row * RPAD + c4 * 4), Ak + (size_t)row * K + c4 * 4);
                CP_ASYNC16(smem_u32(dst + ABUF + row * RPAD + c4 * 4), Bk + (size_t)row * K + c4 * 4);
            }
            CP_COMMIT();
            CP_WAIT(1);
        } else {
            CP_WAIT(0);
        }
        __syncthreads();

        const float* As = smem + (kt & 1) * BUFSZ;
        const float* Bs = As + ABUF;

#pragma unroll
        for (int kk = 0; kk < 4; kk++) {
            const int k0 = kk * 8 + (lane & 3);
            const int rA = wm * 64 + (lane >> 2);
            uint32_t a[4][4];
#pragma unroll
            for (int ms = 0; ms < 4; ms++) {
                const float* ap = As + (rA + ms * 16) * RPAD + k0;
                a[ms][0] = to_tf32(ap[0]);
                a[ms][1] = to_tf32(ap[8 * RPAD]);
                a[ms][2] = to_tf32(ap[4]);
                a[ms][3] = to_tf32(ap[8 * RPAD + 4]);
            }
            uint32_t b[4][2];
            const int nB = wn * 32 + (lane >> 2);
#pragma unroll
            for (int ns = 0; ns < 4; ns++) {
                const float* bp = Bs + (nB + ns * 8) * RPAD + k0;
                b[ns][0] = to_tf32(bp[0]);
                b[ns][1] = to_tf32(bp[4]);
            }
#pragma unroll
            for (int ms = 0; ms < 4; ms++)
#pragma unroll
                for (int ns = 0; ns < 4; ns++) {
                    asm volatile(
                        "mma.sync.aligned.m16n8k8.row.col.f32.tf32.tf32.f32 "
                        "{%0,%1,%2,%3}, {%4,%5,%6,%7}, {%8,%9}, {%0,%1,%2,%3};"
                        : "+f"(acc[ms][ns][0]), "+f"(acc[ms][ns][1]),
                          "+f"(acc[ms][ns][2]), "+f"(acc[ms][ns][3])
                        : "r"(a[ms][0]), "r"(a[ms][1]), "r"(a[ms][2]), "r"(a[ms][3]),
                          "r"(b[ns][0]), "r"(b[ns][1]));
                }
        }
        __syncthreads();
    }

#pragma unroll
    for (int ms = 0; ms < 4; ms++) {
        int row = by * 128 + wm * 64 + ms * 16 + (lane >> 2);
#pragma unroll
        for (int ns = 0; ns < 4; ns++) {
            int col = bx * 128 + wn * 32 + ns * 8 + (lane & 3) * 2;
            float2 bb = make_float2(0.f, 0.f);
            if (bias) bb = *(const float2*)(bias + col);
            {
                float2 v = make_float2(acc[ms][ns][0] + bb.x, acc[ms][ns][1] + bb.y);
                if (Dadd) {
                    float2 dd = *(const float2*)(Dadd + (size_t)row * N + col);
                    v.x += dd.x; v.y += dd.y;
                }
                *(float2*)(C + (size_t)row * N + col) = v;
            }
            {
                float2 v = make_float2(acc[ms][ns][2] + bb.x, acc[ms][ns][3] + bb.y);
                if (Dadd) {
                    float2 dd = *(const float2*)(Dadd + (size_t)(row + 8) * N + col);
                    v.x += dd.x; v.y += dd.y;
                }
                *(float2*)(C + (size_t)(row + 8) * N + col) = v;
            }
        }
    }
}

// ---------------- small utility kernels ----------------
__global__ void zero_kernel(float* p, size_t n) {
    size_t i = (size_t)blockIdx.x * blockDim.x + threadIdx.x;
    if (i < n) p[i] = 0.0f;
}

__global__ void pack_wihc_kernel(const float* __restrict__ src, float* __restrict__ dst) {
    int n = blockIdx.x;
    for (int k = threadIdx.x; k < CDP; k += blockDim.x)
        dst[n * CDP + k] = (k < CD) ? src[n * CD + k] : 0.0f;
}

__global__ void pack_wihw_kernel(const float* __restrict__ src, float* __restrict__ dst) {
    int n = blockIdx.x;
    for (int k = threadIdx.x; k < WDINP; k += blockDim.x)
        dst[n * WDINP + k] = (k < WDIN) ? src[n * WDIN + k] : 0.0f;
}

__global__ void bias_sum_kernel(const float* __restrict__ a, const float* __restrict__ b,
                                float* __restrict__ o) {
    int i = blockIdx.x * blockDim.x + threadIdx.x;
    if (i < G4) o[i] = a[i] + b[i];
}

__global__ void gather_char_kernel(const int* __restrict__ cseq, const float* __restrict__ cemb,
                                   float* __restrict__ Xc) {
    int id = blockIdx.x;            // id = t*W + w
    int t = id >> 13;
    int w = id & (W - 1);
    int ci = cseq[w * LC + t];
    float* dst = Xc + (size_t)id * CDP;
    const float* src = cemb + (size_t)ci * CD;
    for (int k = threadIdx.x; k < CDP; k += blockDim.x)
        dst[k] = (k < CD) ? src[k] : 0.0f;
}

__global__ void gather_word_kernel(const int* __restrict__ wseq, const float* __restrict__ wemb,
                                   const float* __restrict__ Hf, const float* __restrict__ Hb,
                                   float* __restrict__ WX) {
    int w = blockIdx.x;
    int wi = wseq[w];
    float* dst = WX + (size_t)w * WDINP;
    for (int k = threadIdx.x; k < WDINP; k += blockDim.x) {
        float v;
        if (k < WD)            v = wemb[(size_t)wi * WD + k];
        else if (k < WD + HH)  v = Hf[(size_t)w * HH + (k - WD)];
        else if (k < WDIN)     v = Hb[(size_t)w * HH + (k - WD - HH)];
        else                   v = 0.0f;
        dst[k] = v;
    }
}

// ---------------- char LSTM pointwise update, both directions ----------------
__global__ void char_update_dual_kernel(const int* __restrict__ lens,
                                        float* __restrict__ Hf, float* __restrict__ Hb,
                                        float* __restrict__ Cf, float* __restrict__ Cb,
                                        int tf, int tb)
{
    int dir = blockIdx.y;
    int idx = blockIdx.x * blockDim.x + threadIdx.x;   // w*256 + j
    int w = idx >> 8;
    int j = idx & 255;
    int t = dir ? tb : tf;
    if (t >= lens[w]) return;
    const float* gr = g_Gc[dir] + (size_t)w * G4;
    float* Hs = dir ? Hb : Hf;
    float* Cs = dir ? Cb : Cf;
    float gi = gr[j], gf = gr[256 + j], gg = gr[512 + j], go = gr[768 + j];
    float c = Cs[idx];
    float cn = fast_sigmoid(gf) * c + fast_sigmoid(gi) * fast_tanh(gg);
    float hn = fast_sigmoid(go) * fast_tanh(cn);
    Hs[idx] = hn;
    Cs[idx] = cn;
}

// ---------------- sequential word BiLSTM: 8-CTA clusters, DSMEM exchange, 512 threads ------
// Same architecture as the round-11 WIN; only change: 512 threads/CTA so the per-step
// matvec halves to 64 FFMAs per thread (issue ~128 cy vs ~256). tid = r*4 + q:
// r = local gate row (0..127), q = h-quarter (64 floats). Thread holds
// Whh[(r>>5)*256 + b*32 + (r&31)][q*64 .. +64) in 64 registers. Reduce via 2x shfl_xor
// (lanes differ in bits 0-1). Gates on tid<32; DSMEM pushes + split cluster barrier.
__global__ __launch_bounds__(512, 1) __cluster_dims__(CLUST, 1, 1)
void word_lstm_kernel(const float* __restrict__ XGw,
                      const float* __restrict__ WhhF, const float* __restrict__ WhhB,
                      float* __restrict__ OUT)
{
    const int d = blockIdx.x >> 3;          // direction (cluster id)
    const int b = blockIdx.x & 7;           // rank within cluster
    const int tid = threadIdx.x;
    const int r = tid >> 2;                 // local gate row 0..127
    const int q = tid & 3;                  // h quarter
    const int g = r >> 5, jj = r & 31;
    const int rowg = (g << 8) + b * CELLS + jj;

    const float* Whh = d ? WhhB : WhhF;
    const float* xgbase = XGw + (size_t)d * W * G4;

    __shared__ ALN float h_sh[2][HH];       // double-buffered; peers write via DSMEM
    __shared__ ALN float gsh[128];

    float wreg[64];
#pragma unroll
    for (int i = 0; i < 64; i += 4) {
        float4 v = *(const float4*)(Whh + (size_t)rowg * HH + q * 64 + i);
        wreg[i] = v.x; wreg[i + 1] = v.y; wreg[i + 2] = v.z; wreg[i + 3] = v.w;
    }
    if (tid < 2 * HH) ((float*)h_sh)[tid] = 0.0f;
    float c = 0.0f;
    __syncthreads();
    CLUSTER_ARRIVE();                       // all h buffers zeroed before any peer writes
    CLUSTER_WAIT();

    float xg_cur = 0.0f;
    if (q == 0) xg_cur = __ldg(xgbase + (size_t)(d ? (W - 1) : 0) * G4 + rowg);

    for (int t = 0; t < W; t++) {
        const int p = d ? (W - 1 - t) : t;
        const int buf = t & 1;
        const int nb = buf ^ 1;

        // prefetch next step's xg (hidden under matvec + barrier)
        float xg_next = 0.0f;
        if (q == 0 && t + 1 < W) {
            int pn = d ? (W - 2 - t) : (t + 1);
            xg_next = __ldg(xgbase + (size_t)pn * G4 + rowg);
        }

        // matvec partial: 64 MACs from local smem h copy
        const float* hb = &h_sh[buf][q * 64];
        float s0 = 0.f, s1 = 0.f, s2 = 0.f, s3 = 0.f;
#pragma unroll
        for (int i = 0; i < 64; i += 4) {
            float4 h4 = *(const float4*)(hb + i);
            s0 = fmaf(h4.x, wreg[i],     s0);
            s1 = fmaf(h4.y, wreg[i + 1], s1);
            s2 = fmaf(h4.z, wreg[i + 2], s2);
            s3 = fmaf(h4.w, wreg[i + 3], s3);
        }
        float s = (s0 + s1) + (s2 + s3);
        s += __shfl_xor_sync(0xFFFFFFFFu, s, 1);   // combine quarters (lane bits 0-1)
        s += __shfl_xor_sync(0xFFFFFFFFu, s, 2);
        if (q == 0) gsh[r] = xg_cur + s;
        __syncthreads();

        if (tid < CELLS) {
            float gi = gsh[tid], gf = gsh[32 + tid], gg = gsh[64 + tid], go = gsh[96 + tid];
            float cn = fast_sigmoid(gf) * c + fast_sigmoid(gi) * fast_tanh(gg);
            c = cn;
            float hn = fast_sigmoid(go) * fast_tanh(cn);
            // push h into every cluster CTA's next-parity buffer (incl. self)
            uint32_t laddr = smem_u32(&h_sh[nb][b * CELLS + tid]);
#pragma unroll
            for (int rk = 0; rk < CLUST; rk++) ST_CLUSTER_F32(laddr, rk, hn);
            // OUT store AFTER the pushes: off the critical exchange path
            OUT[(size_t)p * HD + d * HH + b * CELLS + tid] = hn;
        }
        // release my DSMEM stores; acquire everyone's (CTA-wide collective)
        CLUSTER_ARRIVE();
        CLUSTER_WAIT();

        xg_cur = xg_next;
    }
}

// ---------------- heads: logits + log_softmax ----------------
__global__ __launch_bounds__(128) void heads_kernel(
    const float* __restrict__ OUT,
    const float* __restrict__ Wp, const float* __restrict__ bp,
    const float* __restrict__ Wp2, const float* __restrict__ bp2,
    float* __restrict__ out)
{
    int w = blockIdx.x;
    __shared__ ALN float osh[HD];
    __shared__ ALN float lsh[T1 + T2];
    int tid = threadIdx.x;
    int lane = tid & 31, wid = tid >> 5;

    for (int k = tid; k < HD; k += 128) osh[k] = OUT[(size_t)w * HD + k];
    __syncthreads();

    for (int l = wid; l < T1 + T2; l += 4) {
        const float* wr = (l < T1) ? (Wp + (size_t)l * HD) : (Wp2 + (size_t)(l - T1) * HD);
        float s = 0.0f;
#pragma unroll 4
        for (int k = lane; k < HD; k += 32) s = fmaf(osh[k], wr[k], s);
#pragma unroll
        for (int o = 16; o; o >>= 1) s += __shfl_xor_sync(0xFFFFFFFFu, s, o);
        if (lane == 0) lsh[l] = s + ((l < T1) ? bp[l] : bp2[l - T1]);
    }
    __syncthreads();

    if (wid < 2) {
        int T = (wid == 0) ? T1 : T2;
        int base = (wid == 0) ? 0 : T1;
        float* ob = (wid == 0) ? (out + (size_t)w * T1)
                               : (out + (size_t)W * T1 + (size_t)w * T2);
        float mx = -1e30f;
        for (int l = lane; l < T; l += 32) mx = fmaxf(mx, lsh[base + l]);
#pragma unroll
        for (int o = 16; o; o >>= 1) mx = fmaxf(mx, __shfl_xor_sync(0xFFFFFFFFu, mx, o));
        float se = 0.0f;
        for (int l = lane; l < T; l += 32) se += expf(lsh[base + l] - mx);
#pragma unroll
        for (int o = 16; o; o >>= 1) se += __shfl_xor_sync(0xFFFFFFFFu, se, o);
        float lz = mx + logf(se);
        for (int l = lane; l < T; l += 32) ob[l] = lsh[base + l] - lz;
    }
}

// ---------------- host orchestration ----------------
static void* sym(const void* s) {
    void* p = nullptr;
    cudaGetSymbolAddress(&p, s);
    return p;
}

extern "C" void kernel_launch(void* const* d_in, const int* in_sizes, int n_in,
                              void* d_out, int out_size)
{
    const int*   wseq  = (const int*)d_in[0];
    const int*   cseq  = (const int*)d_in[1];
    const int*   lens  = (const int*)d_in[2];
    const float* cemb  = (const float*)d_in[3];
    const float* wemb  = (const float*)d_in[4];
    const float* cfWih = (const float*)d_in[5];
    const float* cfWhh = (const float*)d_in[6];
    const float* cfbih = (const float*)d_in[7];
    const float* cfbhh = (const float*)d_in[8];
    const float* cbWih = (const float*)d_in[9];
    const float* cbWhh = (const float*)d_in[10];
    const float* cbbih = (const float*)d_in[11];
    const float* cbbhh = (const float*)d_in[12];
    const float* wfWih = (const float*)d_in[13];
    const float* wfWhh = (const float*)d_in[14];
    const float* wfbih = (const float*)d_in[15];
    const float* wfbhh = (const float*)d_in[16];
    const float* wbWih = (const float*)d_in[17];
    const float* wbWhh = (const float*)d_in[18];
    const float* wbbih = (const float*)d_in[19];
    const float* wbbhh = (const float*)d_in[20];
    const float* Wp    = (const float*)d_in[21];
    const float* bp    = (const float*)d_in[22];
    const float* Wp2   = (const float*)d_in[23];
    const float* bp2   = (const float*)d_in[24];
    float* outp = (float*)d_out;

    float* Xc   = (float*)sym(g_Xc);
    float* XGf  = (float*)sym(g_XGf);
    float* XGb  = (float*)sym(g_XGb);
    float* Gc   = (float*)sym(g_Gc);
    float* HC   = (float*)sym(g_HC);
    float* WX   = (float*)sym(g_WX);
    float* XGw  = (float*)sym(g_XGw);
    float* OUT  = (float*)sym(g_OUT);
    float* WihC = (float*)sym(g_WihC);
    float* WihW = (float*)sym(g_WihW);
    float* bias = (float*)sym(g_bias);

    float* Hf = HC + 0 * (size_t)W * HH;
    float* Hb = HC + 1 * (size_t)W * HH;
    float* Cf = HC + 2 * (size_t)W * HH;
    float* Cb = HC + 3 * (size_t)W * HH;
    float* Gc0 = Gc;
    float* Gc1 = Gc + (size_t)W * G4;

    cudaFuncSetAttribute(gemm_mma_dual_kernel, cudaFuncAttributeMaxDynamicSharedMemorySize,
                         GEMM_SMEM_BYTES);

    // ---- pack weights / biases ----
    pack_wihc_kernel<<<G4, 128>>>(cfWih, WihC + 0 * (size_t)G4 * CDP);
    pack_wihc_kernel<<<G4, 128>>>(cbWih, WihC + 1 * (size_t)G4 * CDP);
    pack_wihw_kernel<<<G4, 256>>>(wfWih, WihW + 0 * (size_t)G4 * WDINP);
    pack_wihw_kernel<<<G4, 256>>>(wbWih, WihW + 1 * (size_t)G4 * WDINP);
    bias_sum_kernel<<<4, 256>>>(cfbih, cfbhh, bias + 0 * G4);
    bias_sum_kernel<<<4, 256>>>(cbbih, cbbhh, bias + 1 * G4);
    bias_sum_kernel<<<4, 256>>>(wfbih, wfbhh, bias + 2 * G4);
    bias_sum_kernel<<<4, 256>>>(wbbih, wbbhh, bias + 3 * G4);

    // ---- gather char embeddings ----
    gather_char_kernel<<<LC * W, 128>>>(cseq, cemb, Xc);

    // ---- char BiLSTM, both directions together ----
    const size_t nState = (size_t)4 * W * HH;
    zero_kernel<<<(unsigned)((nState + 255) / 256), 256>>>(HC, nState);

    gemm_mma_dual_kernel<<<dim3(G4 / 128, (LC * W) / 128, 2), 256, GEMM_SMEM_BYTES>>>(
        Xc, Xc, WihC, WihC + (size_t)G4 * CDP, bias, bias + G4,
        nullptr, nullptr, XGf, XGb, G4, CDP);

    for (int s = 0; s < LC; s++) {
        int tf = s, tb = LC - 1 - s;
        gemm_mma_dual_kernel<<<dim3(G4 / 128, W / 128, 2), 256, GEMM_SMEM_BYTES>>>(
            Hf, Hb, cfWhh, cbWhh, nullptr, nullptr,
            XGf + (size_t)tf * W * G4, XGb + (size_t)tb * W * G4,
            Gc0, Gc1, G4, HH);
        char_update_dual_kernel<<<dim3((W * HH) / 256, 2), 256>>>(
            lens, Hf, Hb, Cf, Cb, tf, tb);
    }

    // ---- word-level input ----
    gather_word_kernel<<<W, 256>>>(wseq, wemb, Hf, Hb, WX);
    gemm_mma_dual_kernel<<<dim3(G4 / 128, W / 128, 2), 256, GEMM_SMEM_BYTES>>>(
        WX, WX, WihW, WihW + (size_t)G4 * WDINP, bias + 2 * G4, bias + 3 * G4,
        nullptr, nullptr, XGw, XGw + (size_t)W * G4, G4, WDINP);

    // ---- sequential word BiLSTM: 2 clusters of 8 CTAs, DSMEM exchange, 512 thr ----
    word_lstm_kernel<<<2 * CLUST, 512>>>(XGw, wfWhh, wbWhh, OUT);

    // ---- heads + log_softmax ----
    heads_kernel<<<W, 128>>>(OUT, Wp, bp, Wp2, bp2, outp);

    (void)in_sizes; (void)n_in; (void)out_size;
}

// round 15
// speedup vs baseline: 2.2236x; 2.2236x over previous
#include <cuda_runtime.h>
#include <math.h>
#include <stdint.h>

// ---------------- problem constants ----------------
#define W     8192      // words
#define LC    16        // chars per word (padded)
#define CD    100       // char emb dim
#define CDP   128       // padded to %32 for tensor GEMM
#define WD    300       // word emb dim
#define HD    512       // hidden dim (bi)
#define HH    256       // per-direction hidden
#define G4    1024      // 4*HH gates
#define WDIN  812       // WD + HD
#define WDINP 832       // padded to %32
#define T1    48
#define T2    32

#define CLUST    8      // word-lstm CTAs per direction (one cluster)
#define CELLS    32     // cells per CTA

#define ALN __align__(16)

// smem layout constants for GEMM (floats)
#define KCH   32
#define RPAD  36
#define ABUF  (128 * RPAD)
#define BUFSZ (2 * ABUF)
#define GEMM_SMEM_BYTES (2 * BUFSZ * 4)   // 73728 B

// ---------------- static device scratch (no cudaMalloc allowed) ----------------
__device__ ALN float g_Xc[(size_t)LC * W * CDP];
__device__ ALN float g_XGf[(size_t)LC * W * G4];      // char input gates, fwd
__device__ ALN float g_XGb[(size_t)LC * W * G4];      // char input gates, bwd
__device__ ALN float g_Gc[2][(size_t)W * G4];         // per-step gate scratch (both dirs)
__device__ ALN float g_HC[4][(size_t)W * HH];         // Hf, Hb, Cf, Cb
__device__ ALN float g_WX[(size_t)W * WDINP];
__device__ ALN float g_XGw[(size_t)2 * W * G4];
__device__ ALN float g_OUT[(size_t)W * HD];
__device__ ALN float g_WihC[2][G4 * CDP];
__device__ ALN float g_WihW[2][G4 * WDINP];
__device__ ALN float g_bias[4][G4];

__device__ __forceinline__ float fast_sigmoid(float x) {
    return __fdividef(1.0f, 1.0f + __expf(-x));
}
__device__ __forceinline__ float fast_tanh(float x) {
    return 1.0f - __fdividef(2.0f, __expf(2.0f * x) + 1.0f);
}

__device__ __forceinline__ uint32_t smem_u32(const void* p) {
    uint32_t a;
    asm("{ .reg .u64 t; cvta.to.shared.u64 t, %1; cvt.u32.u64 %0, t; }" : "=r"(a) : "l"(p));
    return a;
}
__device__ __forceinline__ uint32_t to_tf32(float x) {
    uint32_t u;
    asm("cvt.rna.tf32.f32 %0, %1;" : "=r"(u) : "f"(x));
    return u;
}
#define CP_ASYNC16(dst, src) \
    asm volatile("cp.async.cg.shared.global [%0], [%1], 16;" :: "r"(dst), "l"(src) : "memory")
#define CP_COMMIT()  asm volatile("cp.async.commit_group;" ::: "memory")
#define CP_WAIT(n)   asm volatile("cp.async.wait_group %0;" :: "n"(n) : "memory")

// cluster barrier (split) and DSMEM store
#define CLUSTER_ARRIVE() asm volatile("barrier.cluster.arrive.aligned;" ::: "memory")
#define CLUSTER_WAIT()   asm volatile("barrier.cluster.wait.aligned;" ::: "memory")
#define ST_CLUSTER_F32(local_addr, rank, val)                                         \
    asm volatile("{\n\t.reg .b32 ra;\n\t"                                             \
                 "mapa.shared::cluster.u32 ra, %0, %1;\n\t"                           \
                 "st.shared::cluster.f32 [ra], %2;\n\t}"                              \
                 :: "r"(local_addr), "r"(rank), "f"(val) : "memory")

// packed fp32x2 helpers (PTX ISA 8.6, sm_100+)
#define PACK_F32X2(out, lo, hi) \
    asm("mov.b64 %0, {%1, %2};" : "=l"(out) : "f"(lo), "f"(hi))
#define UNPACK_F32X2(lo, hi, in) \
    asm("mov.b64 {%0, %1}, %2;" : "=f"(lo), "=f"(hi) : "l"(in))
#define FMA_F32X2(acc, a, b) \
    asm("fma.rn.f32x2 %0, %1, %2, %0;" : "+l"(acc) : "l"(a), "l"(b))

// ---------------- TF32 mma.sync dual GEMM ----------------
__global__ __launch_bounds__(256, 2)
void gemm_mma_dual_kernel(const float* __restrict__ A0, const float* __restrict__ A1,
                          const float* __restrict__ B0, const float* __restrict__ B1,
                          const float* __restrict__ bias0, const float* __restrict__ bias1,
                          const float* __restrict__ D0, const float* __restrict__ D1,
                          float* __restrict__ C0, float* __restrict__ C1,
                          int N, int K)
{
    extern __shared__ ALN float smem[];

    const int tid = threadIdx.x;
    const int lane = tid & 31, wid = tid >> 5;
    const int wm = wid & 1, wn = wid >> 1;
    const int bx = blockIdx.x, by = blockIdx.y, bz = blockIdx.z;

    const float* A    = bz ? A1 : A0;
    const float* B    = bz ? B1 : B0;
    const float* bias = bz ? bias1 : bias0;
    const float* Dadd = bz ? D1 : D0;
    float*       C    = bz ? C1 : C0;

    const float* Abase = A + (size_t)(by * 128) * K;
    const float* Bbase = B + (size_t)(bx * 128) * K;

    float acc[4][4][4];
#pragma unroll
    for (int i = 0; i < 4; i++)
#pragma unroll
        for (int j = 0; j < 4; j++)
#pragma unroll
            for (int q = 0; q < 4; q++) acc[i][j][q] = 0.0f;

    const int nkt = K >> 5;

    {
        float* dst = smem;
#pragma unroll
        for (int i = 0; i < 4; i++) {
            int f = tid + i * 256;
            int row = f >> 3, c4 = f & 7;
            CP_ASYNC16(smem_u32(dst + row * RPAD + c4 * 4), Abase + (size_t)row * K + c4 * 4);
            CP_ASYNC16(smem_u32(dst + ABUF + row * RPAD + c4 * 4), Bbase + (size_t)row * K + c4 * 4);
        }
        CP_COMMIT();
    }

    for (int kt = 0; kt < nkt; kt++) {
        if (kt + 1 < nkt) {
            float* dst = smem + ((kt + 1) & 1) * BUFSZ;
            const float* Ak = Abase + (kt + 1) * KCH;
            const float* Bk = Bbase + (kt + 1) * KCH;
#pragma unroll
            for (int i = 0; i < 4; i++) {
                int f = tid + i * 256;
                int row = f >> 3, c4 = f & 7;
                CP_ASYNC16(smem_u32(dst + row * RPAD + c4 * 4), Ak + (size_t)row * K + c4 * 4);
                CP_ASYNC16(smem_u32(dst + ABUF + row * RPAD + c4 * 4), Bk + (size_t)row * K + c4 * 4);
            }
            CP_COMMIT();
            CP_WAIT(1);
        } else {
            CP_WAIT(0);
        }
        __syncthreads();

        const float* As = smem + (kt & 1) * BUFSZ;
        const float* Bs = As + ABUF;

#pragma unroll
        for (int kk = 0; kk < 4; kk++) {
            const int k0 = kk * 8 + (lane & 3);
            const int rA = wm * 64 + (lane >> 2);
            uint32_t a[4][4];
#pragma unroll
            for (int ms = 0; ms < 4; ms++) {
                const float* ap = As + (rA + ms * 16) * RPAD + k0;
                a[ms][0] = to_tf32(ap[0]);
                a[ms][1] = to_tf32(ap[8 * RPAD]);
                a[ms][2] = to_tf32(ap[4]);
                a[ms][3] = to_tf32(ap[8 * RPAD + 4]);
            }
            uint32_t b[4][2];
            const int nB = wn * 32 + (lane >> 2);
#pragma unroll
            for (int ns = 0; ns < 4; ns++) {
                const float* bp = Bs + (nB + ns * 8) * RPAD + k0;
                b[ns][0] = to_tf32(bp[0]);
                b[ns][1] = to_tf32(bp[4]);
            }
#pragma unroll
            for (int ms = 0; ms < 4; ms++)
#pragma unroll
                for (int ns = 0; ns < 4; ns++) {
                    asm volatile(
                        "mma.sync.aligned.m16n8k8.row.col.f32.tf32.tf32.f32 "
                        "{%0,%1,%2,%3}, {%4,%5,%6,%7}, {%8,%9}, {%0,%1,%2,%3};"
                        : "+f"(acc[ms][ns][0]), "+f"(acc[ms][ns][1]),
                          "+f"(acc[ms][ns][2]), "+f"(acc[ms][ns][3])
                        : "r"(a[ms][0]), "r"(a[ms][1]), "r"(a[ms][2]), "r"(a[ms][3]),
                          "r"(b[ns][0]), "r"(b[ns][1]));
                }
        }
        __syncthreads();
    }

#pragma unroll
    for (int ms = 0; ms < 4; ms++) {
        int row = by * 128 + wm * 64 + ms * 16 + (lane >> 2);
#pragma unroll
        for (int ns = 0; ns < 4; ns++) {
            int col = bx * 128 + wn * 32 + ns * 8 + (lane & 3) * 2;
            float2 bb = make_float2(0.f, 0.f);
            if (bias) bb = *(const float2*)(bias + col);
            {
                float2 v = make_float2(acc[ms][ns][0] + bb.x, acc[ms][ns][1] + bb.y);
                if (Dadd) {
                    float2 dd = *(const float2*)(Dadd + (size_t)row * N + col);
                    v.x += dd.x; v.y += dd.y;
                }
                *(float2*)(C + (size_t)row * N + col) = v;
            }
            {
                float2 v = make_float2(acc[ms][ns][2] + bb.x, acc[ms][ns][3] + bb.y);
                if (Dadd) {
                    float2 dd = *(const float2*)(Dadd + (size_t)(row + 8) * N + col);
                    v.x += dd.x; v.y += dd.y;
                }
                *(float2*)(C + (size_t)(row + 8) * N + col) = v;
            }
        }
    }
}

// ---------------- small utility kernels ----------------
__global__ void zero_kernel(float* p, size_t n) {
    size_t i = (size_t)blockIdx.x * blockDim.x + threadIdx.x;
    if (i < n) p[i] = 0.0f;
}

__global__ void pack_wihc_kernel(const float* __restrict__ src, float* __restrict__ dst) {
    int n = blockIdx.x;
    for (int k = threadIdx.x; k < CDP; k += blockDim.x)
        dst[n * CDP + k] = (k < CD) ? src[n * CD + k] : 0.0f;
}

__global__ void pack_wihw_kernel(const float* __restrict__ src, float* __restrict__ dst) {
    int n = blockIdx.x;
    for (int k = threadIdx.x; k < WDINP; k += blockDim.x)
        dst[n * WDINP + k] = (k < WDIN) ? src[n * WDIN + k] : 0.0f;
}

__global__ void bias_sum_kernel(const float* __restrict__ a, const float* __restrict__ b,
                                float* __restrict__ o) {
    int i = blockIdx.x * blockDim.x + threadIdx.x;
    if (i < G4) o[i] = a[i] + b[i];
}

__global__ void gather_char_kernel(const int* __restrict__ cseq, const float* __restrict__ cemb,
                                   float* __restrict__ Xc) {
    int id = blockIdx.x;            // id = t*W + w
    int t = id >> 13;
    int w = id & (W - 1);
    int ci = cseq[w * LC + t];
    float* dst = Xc + (size_t)id * CDP;
    const float* src = cemb + (size_t)ci * CD;
    for (int k = threadIdx.x; k < CDP; k += blockDim.x)
        dst[k] = (k < CD) ? src[k] : 0.0f;
}

__global__ void gather_word_kernel(const int* __restrict__ wseq, const float* __restrict__ wemb,
                                   const float* __restrict__ Hf, const float* __restrict__ Hb,
                                   float* __restrict__ WX) {
    int w = blockIdx.x;
    int wi = wseq[w];
    float* dst = WX + (size_t)w * WDINP;
    for (int k = threadIdx.x; k < WDINP; k += blockDim.x) {
        float v;
        if (k < WD)            v = wemb[(size_t)wi * WD + k];
        else if (k < WD + HH)  v = Hf[(size_t)w * HH + (k - WD)];
        else if (k < WDIN)     v = Hb[(size_t)w * HH + (k - WD - HH)];
        else                   v = 0.0f;
        dst[k] = v;
    }
}

// ---------------- char LSTM pointwise update, both directions ----------------
__global__ void char_update_dual_kernel(const int* __restrict__ lens,
                                        float* __restrict__ Hf, float* __restrict__ Hb,
                                        float* __restrict__ Cf, float* __restrict__ Cb,
                                        int tf, int tb)
{
    int dir = blockIdx.y;
    int idx = blockIdx.x * blockDim.x + threadIdx.x;   // w*256 + j
    int w = idx >> 8;
    int j = idx & 255;
    int t = dir ? tb : tf;
    if (t >= lens[w]) return;
    const float* gr = g_Gc[dir] + (size_t)w * G4;
    float* Hs = dir ? Hb : Hf;
    float* Cs = dir ? Cb : Cf;
    float gi = gr[j], gf = gr[256 + j], gg = gr[512 + j], go = gr[768 + j];
    float c = Cs[idx];
    float cn = fast_sigmoid(gf) * c + fast_sigmoid(gi) * fast_tanh(gg);
    float hn = fast_sigmoid(go) * fast_tanh(cn);
    Hs[idx] = hn;
    Cs[idx] = cn;
}

// ---------------- sequential word BiLSTM: 8-CTA clusters, DSMEM exchange ----------------
// Round-11 WIN architecture (256 threads, barrier.cluster sync) with two local changes:
// 1) matvec uses packed fma.rn.f32x2 (h read from smem as ulonglong2, weights pre-packed
//    into u64 pairs): 3 instr per 4 MACs instead of 5 -> matvec issue ~512 -> ~310 cy.
//    Bitwise-identical numerics (IEEE fp32 FMA per lane, same order).
// 2) OUT store moved between CLUSTER_ARRIVE and CLUSTER_WAIT (off the rendezvous path).
__global__ __launch_bounds__(256, 1) __cluster_dims__(CLUST, 1, 1)
void word_lstm_kernel(const float* __restrict__ XGw,
                      const float* __restrict__ WhhF, const float* __restrict__ WhhB,
                      float* __restrict__ OUT)
{
    const int d = blockIdx.x >> 3;          // direction (cluster id)
    const int b = blockIdx.x & 7;           // rank within cluster
    const int tid = threadIdx.x;
    const int r = tid >> 1;                 // local row 0..127
    const int half = tid & 1;
    const int g = r >> 5, jj = r & 31;
    const int rowg = (g << 8) + b * CELLS + jj;

    const float* Whh = d ? WhhB : WhhF;
    const float* xgbase = XGw + (size_t)d * W * G4;

    __shared__ ALN float h_sh[2][HH];       // double-buffered; peers write via DSMEM
    __shared__ ALN float gsh[128];

    // weights packed as 64 u64 pairs (w[2k], w[2k+1])
    unsigned long long wpk[64];
#pragma unroll
    for (int i = 0; i < 128; i += 4) {
        float4 v = *(const float4*)(Whh + (size_t)rowg * HH + half * 128 + i);
        PACK_F32X2(wpk[(i >> 1) + 0], v.x, v.y);
        PACK_F32X2(wpk[(i >> 1) + 1], v.z, v.w);
    }
    ((float*)h_sh)[tid] = 0.0f;
    ((float*)h_sh)[tid + 256] = 0.0f;
    float c = 0.0f;
    __syncthreads();
    CLUSTER_ARRIVE();                       // all h buffers zeroed before any peer writes
    CLUSTER_WAIT();

    float xg_cur = 0.0f;
    if (half == 0) xg_cur = __ldg(xgbase + (size_t)(d ? (W - 1) : 0) * G4 + rowg);

    for (int t = 0; t < W; t++) {
        const int p = d ? (W - 1 - t) : t;
        const int buf = t & 1;
        const int nb = buf ^ 1;

        // prefetch next step's xg (hidden under matvec + barrier)
        float xg_next = 0.0f;
        if (half == 0 && t + 1 < W) {
            int pn = d ? (W - 2 - t) : (t + 1);
            xg_next = __ldg(xgbase + (size_t)pn * G4 + rowg);
        }

        // matvec partial: 128 MACs via 64 packed f32x2 FMAs
        const float* hb = &h_sh[buf][half * 128];
        unsigned long long a01 = 0ull, a23 = 0ull;   // two (+0.0f,+0.0f) accumulators
#pragma unroll
        for (int i = 0; i < 128; i += 4) {
            ulonglong2 hp = *(const ulonglong2*)(hb + i);
            FMA_F32X2(a01, hp.x, wpk[(i >> 1) + 0]);
            FMA_F32X2(a23, hp.y, wpk[(i >> 1) + 1]);
        }
        float f0, f1, f2, f3;
        UNPACK_F32X2(f0, f1, a01);
        UNPACK_F32X2(f2, f3, a23);
        float s = (f0 + f1) + (f2 + f3);
        s += __shfl_xor_sync(0xFFFFFFFFu, s, 1);   // combine the two halves
        if (half == 0) gsh[r] = xg_cur + s;
        __syncthreads();

        float hn_out = 0.0f;
        if (tid < CELLS) {
            float gi = gsh[tid], gf = gsh[32 + tid], gg = gsh[64 + tid], go = gsh[96 + tid];
            float cn = fast_sigmoid(gf) * c + fast_sigmoid(gi) * fast_tanh(gg);
            c = cn;
            float hn = fast_sigmoid(go) * fast_tanh(cn);
            hn_out = hn;
            // push h into every cluster CTA's next-parity buffer (incl. self)
            uint32_t laddr = smem_u32(&h_sh[nb][b * CELLS + tid]);
#pragma unroll
            for (int rk = 0; rk < CLUST; rk++) ST_CLUSTER_F32(laddr, rk, hn);
        }
        // release my DSMEM stores (gsh reads above also complete before this)
        CLUSTER_ARRIVE();
        // DRAM-bound OUT store between arrive and wait: off the rendezvous path
        if (tid < CELLS)
            OUT[(size_t)p * HD + d * HH + b * CELLS + tid] = hn_out;
        CLUSTER_WAIT();

        xg_cur = xg_next;
    }
}

// ---------------- heads: logits + log_softmax ----------------
__global__ __launch_bounds__(128) void heads_kernel(
    const float* __restrict__ OUT,
    const float* __restrict__ Wp, const float* __restrict__ bp,
    const float* __restrict__ Wp2, const float* __restrict__ bp2,
    float* __restrict__ out)
{
    int w = blockIdx.x;
    __shared__ ALN float osh[HD];
    __shared__ ALN float lsh[T1 + T2];
    int tid = threadIdx.x;
    int lane = tid & 31, wid = tid >> 5;

    for (int k = tid; k < HD; k += 128) osh[k] = OUT[(size_t)w * HD + k];
    __syncthreads();

    for (int l = wid; l < T1 + T2; l += 4) {
        const float* wr = (l < T1) ? (Wp + (size_t)l * HD) : (Wp2 + (size_t)(l - T1) * HD);
        float s = 0.0f;
#pragma unroll 4
        for (int k = lane; k < HD; k += 32) s = fmaf(osh[k], wr[k], s);
#pragma unroll
        for (int o = 16; o; o >>= 1) s += __shfl_xor_sync(0xFFFFFFFFu, s, o);
        if (lane == 0) lsh[l] = s + ((l < T1) ? bp[l] : bp2[l - T1]);
    }
    __syncthreads();

    if (wid < 2) {
        int T = (wid == 0) ? T1 : T2;
        int base = (wid == 0) ? 0 : T1;
        float* ob = (wid == 0) ? (out + (size_t)w * T1)
                               : (out + (size_t)W * T1 + (size_t)w * T2);
        float mx = -1e30f;
        for (int l = lane; l < T; l += 32) mx = fmaxf(mx, lsh[base + l]);
#pragma unroll
        for (int o = 16; o; o >>= 1) mx = fmaxf(mx, __shfl_xor_sync(0xFFFFFFFFu, mx, o));
        float se = 0.0f;
        for (int l = lane; l < T; l += 32) se += expf(lsh[base + l] - mx);
#pragma unroll
        for (int o = 16; o; o >>= 1) se += __shfl_xor_sync(0xFFFFFFFFu, se, o);
        float lz = mx + logf(se);
        for (int l = lane; l < T; l += 32) ob[l] = lsh[base + l] - lz;
    }
}

// ---------------- host orchestration ----------------
static void* sym(const void* s) {
    void* p = nullptr;
    cudaGetSymbolAddress(&p, s);
    return p;
}

extern "C" void kernel_launch(void* const* d_in, const int* in_sizes, int n_in,
                              void* d_out, int out_size)
{
    const int*   wseq  = (const int*)d_in[0];
    const int*   cseq  = (const int*)d_in[1];
    const int*   lens  = (const int*)d_in[2];
    const float* cemb  = (const float*)d_in[3];
    const float* wemb  = (const float*)d_in[4];
    const float* cfWih = (const float*)d_in[5];
    const float* cfWhh = (const float*)d_in[6];
    const float* cfbih = (const float*)d_in[7];
    const float* cfbhh = (const float*)d_in[8];
    const float* cbWih = (const float*)d_in[9];
    const float* cbWhh = (const float*)d_in[10];
    const float* cbbih = (const float*)d_in[11];
    const float* cbbhh = (const float*)d_in[12];
    const float* wfWih = (const float*)d_in[13];
    const float* wfWhh = (const float*)d_in[14];
    const float* wfbih = (const float*)d_in[15];
    const float* wfbhh = (const float*)d_in[16];
    const float* wbWih = (const float*)d_in[17];
    const float* wbWhh = (const float*)d_in[18];
    const float* wbbih = (const float*)d_in[19];
    const float* wbbhh = (const float*)d_in[20];
    const float* Wp    = (const float*)d_in[21];
    const float* bp    = (const float*)d_in[22];
    const float* Wp2   = (const float*)d_in[23];
    const float* bp2   = (const float*)d_in[24];
    float* outp = (float*)d_out;

    float* Xc   = (float*)sym(g_Xc);
    float* XGf  = (float*)sym(g_XGf);
    float* XGb  = (float*)sym(g_XGb);
    float* Gc   = (float*)sym(g_Gc);
    float* HC   = (float*)sym(g_HC);
    float* WX   = (float*)sym(g_WX);
    float* XGw  = (float*)sym(g_XGw);
    float* OUT  = (float*)sym(g_OUT);
    float* WihC = (float*)sym(g_WihC);
    float* WihW = (float*)sym(g_WihW);
    float* bias = (float*)sym(g_bias);

    float* Hf = HC + 0 * (size_t)W * HH;
    float* Hb = HC + 1 * (size_t)W * HH;
    float* Cf = HC + 2 * (size_t)W * HH;
    float* Cb = HC + 3 * (size_t)W * HH;
    float* Gc0 = Gc;
    float* Gc1 = Gc + (size_t)W * G4;

    cudaFuncSetAttribute(gemm_mma_dual_kernel, cudaFuncAttributeMaxDynamicSharedMemorySize,
                         GEMM_SMEM_BYTES);

    // ---- pack weights / biases ----
    pack_wihc_kernel<<<G4, 128>>>(cfWih, WihC + 0 * (size_t)G4 * CDP);
    pack_wihc_kernel<<<G4, 128>>>(cbWih, WihC + 1 * (size_t)G4 * CDP);
    pack_wihw_kernel<<<G4, 256>>>(wfWih, WihW + 0 * (size_t)G4 * WDINP);
    pack_wihw_kernel<<<G4, 256>>>(wbWih, WihW + 1 * (size_t)G4 * WDINP);
    bias_sum_kernel<<<4, 256>>>(cfbih, cfbhh, bias + 0 * G4);
    bias_sum_kernel<<<4, 256>>>(cbbih, cbbhh, bias + 1 * G4);
    bias_sum_kernel<<<4, 256>>>(wfbih, wfbhh, bias + 2 * G4);
    bias_sum_kernel<<<4, 256>>>(wbbih, wbbhh, bias + 3 * G4);

    // ---- gather char embeddings ----
    gather_char_kernel<<<LC * W, 128>>>(cseq, cemb, Xc);

    // ---- char BiLSTM, both directions together ----
    const size_t nState = (size_t)4 * W * HH;
    zero_kernel<<<(unsigned)((nState + 255) / 256), 256>>>(HC, nState);

    gemm_mma_dual_kernel<<<dim3(G4 / 128, (LC * W) / 128, 2), 256, GEMM_SMEM_BYTES>>>(
        Xc, Xc, WihC, WihC + (size_t)G4 * CDP, bias, bias + G4,
        nullptr, nullptr, XGf, XGb, G4, CDP);

    for (int s = 0; s < LC; s++) {
        int tf = s, tb = LC - 1 - s;
        gemm_mma_dual_kernel<<<dim3(G4 / 128, W / 128, 2), 256, GEMM_SMEM_BYTES>>>(
            Hf, Hb, cfWhh, cbWhh, nullptr, nullptr,
            XGf + (size_t)tf * W * G4, XGb + (size_t)tb * W * G4,
            Gc0, Gc1, G4, HH);
        char_update_dual_kernel<<<dim3((W * HH) / 256, 2), 256>>>(
            lens, Hf, Hb, Cf, Cb, tf, tb);
    }

    // ---- word-level input ----
    gather_word_kernel<<<W, 256>>>(wseq, wemb, Hf, Hb, WX);
    gemm_mma_dual_kernel<<<dim3(G4 / 128, W / 128, 2), 256, GEMM_SMEM_BYTES>>>(
        WX, WX, WihW, WihW + (size_t)G4 * WDINP, bias + 2 * G4, bias + 3 * G4,
        nullptr, nullptr, XGw, XGw + (size_t)W * G4, G4, WDINP);

    // ---- sequential word BiLSTM: 2 clusters of 8 CTAs, DSMEM exchange ----
    word_lstm_kernel<<<2 * CLUST, 256>>>(XGw, wfWhh, wbWhh, OUT);

    // ---- heads + log_softmax ----
    heads_kernel<<<W, 128>>>(OUT, Wp, bp, Wp2, bp2, outp);

    (void)in_sizes; (void)n_in; (void)out_size;
}